// round 9
// baseline (speedup 1.0000x reference)
#include <cuda_runtime.h>
#include <cuda_fp16.h>
#include <cstdint>

#define B_ 4
#define T_ 256
#define U_ 64
#define D_ 512
#define H_ 512
#define V_ 1024

// ---------------------------------------------------------------------------
// Device-global scratch (allocation-free rule)
// ---------------------------------------------------------------------------
__device__ float g_enc[B_ * T_ * H_];          // 1024 x 512 enc_proj (fp32)
__device__ float g_dec[B_ * U_ * H_];          // 256  x 512 dec_proj + b1 (fp32)
__device__ uint4 g_w2p[4 * 16 * 1024];         // w2 fp16 frag-packed (1 MB)

__device__ __forceinline__ uint32_t f2tf32(float x) {
    uint32_t u; asm("cvt.rna.tf32.f32 %0, %1;" : "=r"(u) : "f"(x)); return u;
}
__device__ __forceinline__ uint32_t packh2(float a, float b) {
    __half2 h = __floats2half2_rn(a, b);
    return *reinterpret_cast<uint32_t*>(&h);
}
__device__ __forceinline__ float gelu_tanh(float x) {
    float t = 0.7978845608028654f * (x + 0.044715f * x * x * x);
    float th; asm("tanh.approx.f32 %0, %1;" : "=f"(th) : "f"(t));
    return 0.5f * x * (1.0f + th);
}
__device__ __forceinline__ uint32_t smem_u32(const void* p) {
    uint32_t a;
    asm("{ .reg .u64 t; cvta.to.shared.u64 t, %1; cvt.u32.u64 %0, t; }" : "=r"(a) : "l"(p));
    return a;
}
__device__ __forceinline__ void mma_tf32(float* acc, uint32_t a0, uint32_t a1,
                                         uint32_t a2, uint32_t a3,
                                         uint32_t b0, uint32_t b1) {
    asm volatile(
        "mma.sync.aligned.m16n8k8.row.col.f32.tf32.tf32.f32 "
        "{%0,%1,%2,%3}, {%4,%5,%6,%7}, {%8,%9}, {%0,%1,%2,%3};"
        : "+f"(acc[0]), "+f"(acc[1]), "+f"(acc[2]), "+f"(acc[3])
        : "r"(a0), "r"(a1), "r"(a2), "r"(a3), "r"(b0), "r"(b1));
}
__device__ __forceinline__ void mma_f16(float* acc, uint32_t a0, uint32_t a1,
                                        uint32_t a2, uint32_t a3,
                                        uint32_t b0, uint32_t b1) {
    asm volatile(
        "mma.sync.aligned.m16n8k16.row.col.f32.f16.f16.f32 "
        "{%0,%1,%2,%3}, {%4,%5,%6,%7}, {%8,%9}, {%0,%1,%2,%3};"
        : "+f"(acc[0]), "+f"(acc[1]), "+f"(acc[2]), "+f"(acc[3])
        : "r"(a0), "r"(a1), "r"(a2), "r"(a3), "r"(b0), "r"(b1));
}
__device__ __forceinline__ void cp16(uint32_t sdst, const void* gsrc) {
    asm volatile("cp.async.cg.shared.global [%0], [%1], 16;" :: "r"(sdst), "l"(gsrc));
}
__device__ __forceinline__ void cp_commit() {
    asm volatile("cp.async.commit_group;" ::: "memory");
}
template <int N>
__device__ __forceinline__ void cp_wait() {
    asm volatile("cp.async.wait_group %0;" :: "n"(N) : "memory");
}

// ---------------------------------------------------------------------------
// prep_kernel (unchanged from R8, 20.7us):
//   blocks 0..159  : enc/dec projections (tf32 mma, M=32 N=128, K=64 chunks)
//   blocks 160..415: w2 -> g_w2p fp16 fragment pack
// ---------------------------------------------------------------------------
#define PA_STRIDE 272
#define PB_STRIDE 272
#define P_OFF_A   0
#define P_OFF_B   17408
#define P_SMEM    87040

__global__ __launch_bounds__(256) void prep_kernel(
    const float* __restrict__ enc, const float* __restrict__ dec,
    const float* __restrict__ w1, const float* __restrict__ b1,
    const float* __restrict__ w2)
{
    const int bid = blockIdx.x;
    const int tid = threadIdx.x;

    if (bid >= 160) {   // ---- w2 fp16 fragment pack ----
        int t  = (bid - 160) * 256 + tid;
        int l  = t & 31;
        int p  = (t >> 5) & 31;
        int ch = (t >> 10) & 15;
        int nt = t >> 14;
        int n  = nt * 256 + p * 8 + (l >> 2);
        int c0 = ch * 32 + (l & 3) * 2;
        const float* r = w2 + (size_t)n * H_;
        float2 v0 = *(const float2*)(r + c0);
        float2 v1 = *(const float2*)(r + c0 + 8);
        float2 v2 = *(const float2*)(r + c0 + 16);
        float2 v3 = *(const float2*)(r + c0 + 24);
        uint4 q;
        q.x = packh2(v0.x, v0.y);
        q.y = packh2(v1.x, v1.y);
        q.z = packh2(v2.x, v2.y);
        q.w = packh2(v3.x, v3.y);
        g_w2p[((size_t)(nt * 16 + ch) * 32 + p) * 32 + l] = q;
        return;
    }

    extern __shared__ char psm[];
    const uint32_t sbase = smem_u32(psm);

    const int ng = bid & 3;
    const int my = bid >> 2;
    const bool is_dec = (my >= 32);
    const float* A = is_dec ? dec : enc;
    const float* W = is_dec ? (w1 + D_) : w1;
    float* out     = is_dec ? g_dec : g_enc;
    const int m0   = (is_dec ? (my - 32) : my) * 32;
    const int n0   = ng * 128;

    const int lane = tid & 31;
    const int w    = tid >> 5;
    const int wm   = w >> 2;
    const int wn   = w & 3;
    float acc[4][4] = {};

    {
        if (tid < 128) {
            int j = tid;
            #pragma unroll
            for (int i = 0; i < 4; i++, j += 128) {
                int r = j >> 4, seg = j & 15;
                cp16(sbase + P_OFF_A + r * PA_STRIDE + seg * 16,
                     A + (size_t)(m0 + r) * D_ + seg * 4);
            }
        }
        int j = tid;
        #pragma unroll
        for (int i = 0; i < 8; i++, j += 256) {
            int r = j >> 4, seg = j & 15;
            cp16(sbase + P_OFF_B + r * PB_STRIDE + seg * 16,
                 W + (size_t)(n0 + r) * (2 * D_) + seg * 4);
        }
        cp_commit();
    }

    for (int cc = 0; cc < 8; cc++) {
        const int s = cc & 1;
        if (cc < 7) {
            const int sn = s ^ 1;
            const int k0 = (cc + 1) * 64;
            if (tid < 128) {
                int j = tid;
                #pragma unroll
                for (int i = 0; i < 4; i++, j += 128) {
                    int r = j >> 4, seg = j & 15;
                    cp16(sbase + P_OFF_A + sn * 8704 + r * PA_STRIDE + seg * 16,
                         A + (size_t)(m0 + r) * D_ + k0 + seg * 4);
                }
            }
            int j = tid;
            #pragma unroll
            for (int i = 0; i < 8; i++, j += 256) {
                int r = j >> 4, seg = j & 15;
                cp16(sbase + P_OFF_B + sn * 34816 + r * PB_STRIDE + seg * 16,
                     W + (size_t)(n0 + r) * (2 * D_) + k0 + seg * 4);
            }
            cp_commit();
            cp_wait<1>();
        } else {
            cp_wait<0>();
        }
        __syncthreads();

        const float* Af = (const float*)(psm + P_OFF_A + s * 8704);
        const float* Bf = (const float*)(psm + P_OFF_B + s * 34816);

        #pragma unroll
        for (int kk = 0; kk < 8; kk++) {
            int ar = wm * 16 + (lane >> 2);
            int ac = kk * 8 + (lane & 3);
            uint32_t a0 = f2tf32(Af[ar * 68 + ac]);
            uint32_t a1 = f2tf32(Af[(ar + 8) * 68 + ac]);
            uint32_t a2 = f2tf32(Af[ar * 68 + ac + 4]);
            uint32_t a3 = f2tf32(Af[(ar + 8) * 68 + ac + 4]);
            #pragma unroll
            for (int nf = 0; nf < 4; nf++) {
                int br = wn * 32 + nf * 8 + (lane >> 2);
                uint32_t b0 = f2tf32(Bf[br * 68 + ac]);
                uint32_t b1 = f2tf32(Bf[br * 68 + ac + 4]);
                mma_tf32(acc[nf], a0, a1, a2, a3, b0, b1);
            }
        }
        __syncthreads();
    }

    int row = m0 + wm * 16 + (lane >> 2);
    #pragma unroll
    for (int nf = 0; nf < 4; nf++) {
        int cg = n0 + wn * 32 + nf * 8 + (lane & 3) * 2;
        float bv0 = is_dec ? b1[cg]     : 0.0f;
        float bv1 = is_dec ? b1[cg + 1] : 0.0f;
        out[(size_t)row * H_ + cg]           = acc[nf][0] + bv0;
        out[(size_t)row * H_ + cg + 1]       = acc[nf][1] + bv1;
        out[(size_t)(row + 8) * H_ + cg]     = acc[nf][2] + bv0;
        out[(size_t)(row + 8) * H_ + cg + 1] = acc[nf][3] + bv1;
    }
}

// ---------------------------------------------------------------------------
// gemm_fused: one CTA per 128-row m-tile (grid 512).
//  Phase 1: generate A = gelu(enc+dec) fp16 frag-packed into 128KB SMEM (once).
//  Phase 2: for nt=0..3, stream B chunks (64 x 16KB linear) through a 4-stage
//           cp.async pipeline; warp tile 64x64, m16n8k16.
// SMEM: A [0, 131072), B stages [131072 + s*16384), s=0..3  => 196608 B.
// ---------------------------------------------------------------------------
#define FA_BYTES  131072
#define FB_STAGE  16384
#define SMEM_F    (FA_BYTES + 4 * FB_STAGE)   // 196608

__global__ __launch_bounds__(256) void gemm_fused(float* __restrict__ out)
{
    extern __shared__ char smem[];
    const uint32_t sbase = smem_u32(smem);
    const int tid  = threadIdx.x;
    const int lane = tid & 31;
    const int w    = tid >> 5;
    const int wm   = w >> 2;          // 0..1 (64 rows)
    const int wn   = w & 3;           // 0..3 (64 cols)
    const int mt   = blockIdx.x;      // 0..511

    // ---- B pipeline prologue: chunks 0,1,2 (one commit each) ----
    const uint4* gB = g_w2p;
    #pragma unroll
    for (int pc = 0; pc < 3; pc++) {
        uint32_t dB = sbase + FA_BYTES + pc * FB_STAGE + tid * 16;
        const uint4* pB = gB + pc * 1024 + tid;
        #pragma unroll
        for (int i = 0; i < 4; i++) cp16(dB + i * 4096, pB + i * 256);
        cp_commit();
    }

    // ---- Phase 1: A generation (fragment order, fp16) ----
    {
        const int l  = tid & 31;
        const int mb = (tid >> 5) & 7;
        const int rl = mb * 16 + (l >> 2);       // tile row (and rl+8)
        const int grow = mt * 128 + rl;
        const int bt   = grow >> 6;
        const int u    = grow & 63;
        const int bat  = grow >> 14;
        const float* ep  = g_enc + (size_t)bt * H_;
        const float* dp0 = g_dec + (size_t)(bat * 64 + u) * H_;
        const float* dp1 = dp0 + 8 * H_;
        uint4* sA = (uint4*)smem;

        #pragma unroll 2
        for (int ch = 0; ch < 16; ch++) {
            #pragma unroll
            for (int ks = 0; ks < 2; ks++) {
                int cb = ch * 32 + ks * 16 + (l & 3) * 2;
                float2 e0 = *(const float2*)(ep + cb);
                float2 e1 = *(const float2*)(ep + cb + 8);
                float2 a0 = *(const float2*)(dp0 + cb);
                float2 a1 = *(const float2*)(dp0 + cb + 8);
                float2 c0 = *(const float2*)(dp1 + cb);
                float2 c1 = *(const float2*)(dp1 + cb + 8);
                uint4 q;
                q.x = packh2(gelu_tanh(e0.x + a0.x), gelu_tanh(e0.y + a0.y));
                q.y = packh2(gelu_tanh(e0.x + c0.x), gelu_tanh(e0.y + c0.y));
                q.z = packh2(gelu_tanh(e1.x + a1.x), gelu_tanh(e1.y + a1.y));
                q.w = packh2(gelu_tanh(e1.x + c1.x), gelu_tanh(e1.y + c1.y));
                sA[(ch * 16 + mb * 2 + ks) * 32 + l] = q;
            }
        }
    }
    __syncthreads();   // A ready for all warps

    // ---- Phase 2: nt loop, linear B chunk pipeline (j = nt*16+ch) ----
    const size_t rbase = (size_t)mt * 128;

    for (int nt = 0; nt < 4; nt++) {
        float acc[4][8][4] = {};

        for (int ch = 0; ch < 16; ch++) {
            const int j = nt * 16 + ch;
            const int s = j & 3;

            cp_wait<2>();        // group j complete (pending <= j+1, j+2)
            __syncthreads();     // all warps done with stage (j-1)&3, data visible

            // prefetch chunk j+3 into stage (j+3)&3  (= (j-1)&3)
            if (j + 3 < 64) {
                uint32_t dB = sbase + FA_BYTES + ((j + 3) & 3) * FB_STAGE + tid * 16;
                const uint4* pB = gB + (j + 3) * 1024 + tid;
                #pragma unroll
                for (int i = 0; i < 4; i++) cp16(dB + i * 4096, pB + i * 256);
            }
            cp_commit();         // commit every iter (possibly empty group)

            const uint4* sA = (const uint4*)smem + ch * 512;
            const uint4* sB = (const uint4*)(smem + FA_BYTES + s * FB_STAGE);

            uint4 bf[8];
            #pragma unroll
            for (int p = 0; p < 8; p++)
                bf[p] = sB[(wn * 8 + p) * 32 + lane];

            #pragma unroll
            for (int ks = 0; ks < 2; ks++) {
                uint4 af[4];
                #pragma unroll
                for (int mb = 0; mb < 4; mb++)
                    af[mb] = sA[((wm * 4 + mb) * 2 + ks) * 32 + lane];
                #pragma unroll
                for (int mb = 0; mb < 4; mb++) {
                    #pragma unroll
                    for (int p = 0; p < 8; p++) {
                        uint32_t b0 = ks ? bf[p].z : bf[p].x;
                        uint32_t b1 = ks ? bf[p].w : bf[p].y;
                        mma_f16(acc[mb][p], af[mb].x, af[mb].y, af[mb].z, af[mb].w,
                                b0, b1);
                    }
                }
            }
        }

        // epilogue for this nt (A/B stages untouched; no sync needed)
        #pragma unroll
        for (int mb = 0; mb < 4; mb++) {
            size_t r = rbase + wm * 64 + mb * 16 + (lane >> 2);
            #pragma unroll
            for (int p = 0; p < 8; p++) {
                int cg = nt * 256 + wn * 64 + p * 8 + (lane & 3) * 2;
                *(float2*)(out + r * V_ + cg) =
                    make_float2(acc[mb][p][0], acc[mb][p][1]);
                *(float2*)(out + (r + 8) * V_ + cg) =
                    make_float2(acc[mb][p][2], acc[mb][p][3]);
            }
        }
    }
}

extern "C" void kernel_launch(void* const* d_in, const int* in_sizes, int n_in,
                              void* d_out, int out_size) {
    const float* enc = (const float*)d_in[0];
    const float* dec = (const float*)d_in[1];
    const float* w1  = (const float*)d_in[2];
    const float* b1  = (const float*)d_in[3];
    const float* w2  = (const float*)d_in[4];
    float* out = (float*)d_out;

    cudaFuncSetAttribute(prep_kernel, cudaFuncAttributeMaxDynamicSharedMemorySize, P_SMEM);
    cudaFuncSetAttribute(gemm_fused, cudaFuncAttributeMaxDynamicSharedMemorySize, SMEM_F);
    prep_kernel<<<416, 256, P_SMEM>>>(enc, dec, w1, b1, w2);
    gemm_fused<<<512, 256, SMEM_F>>>(out);
}

// round 10
// speedup vs baseline: 1.0883x; 1.0883x over previous
#include <cuda_runtime.h>
#include <cuda_fp16.h>
#include <cstdint>

#define B_ 4
#define T_ 256
#define U_ 64
#define D_ 512
#define H_ 512
#define V_ 1024

// ---------------------------------------------------------------------------
// Device-global scratch (allocation-free rule)
// ---------------------------------------------------------------------------
__device__ float g_enc[B_ * T_ * H_];          // 1024 x 512 enc_proj (fp32)
__device__ float g_dec[B_ * U_ * H_];          // 256  x 512 dec_proj + b1 (fp32)
__device__ uint4 g_w2p[4 * 16 * 1024];         // w2 fp16 frag-packed (1 MB)

__device__ __forceinline__ uint32_t f2tf32(float x) {
    uint32_t u; asm("cvt.rna.tf32.f32 %0, %1;" : "=r"(u) : "f"(x)); return u;
}
__device__ __forceinline__ uint32_t packh2(float a, float b) {
    __half2 h = __floats2half2_rn(a, b);
    return *reinterpret_cast<uint32_t*>(&h);
}
__device__ __forceinline__ float gelu_tanh(float x) {
    float t = 0.7978845608028654f * (x + 0.044715f * x * x * x);
    float th; asm("tanh.approx.f32 %0, %1;" : "=f"(th) : "f"(t));
    return 0.5f * x * (1.0f + th);
}
__device__ __forceinline__ uint32_t smem_u32(const void* p) {
    uint32_t a;
    asm("{ .reg .u64 t; cvta.to.shared.u64 t, %1; cvt.u32.u64 %0, t; }" : "=r"(a) : "l"(p));
    return a;
}
__device__ __forceinline__ void mma_tf32(float* acc, uint32_t a0, uint32_t a1,
                                         uint32_t a2, uint32_t a3,
                                         uint32_t b0, uint32_t b1) {
    asm volatile(
        "mma.sync.aligned.m16n8k8.row.col.f32.tf32.tf32.f32 "
        "{%0,%1,%2,%3}, {%4,%5,%6,%7}, {%8,%9}, {%0,%1,%2,%3};"
        : "+f"(acc[0]), "+f"(acc[1]), "+f"(acc[2]), "+f"(acc[3])
        : "r"(a0), "r"(a1), "r"(a2), "r"(a3), "r"(b0), "r"(b1));
}
__device__ __forceinline__ void mma_f16(float* acc, uint32_t a0, uint32_t a1,
                                        uint32_t a2, uint32_t a3,
                                        uint32_t b0, uint32_t b1) {
    asm volatile(
        "mma.sync.aligned.m16n8k16.row.col.f32.f16.f16.f32 "
        "{%0,%1,%2,%3}, {%4,%5,%6,%7}, {%8,%9}, {%0,%1,%2,%3};"
        : "+f"(acc[0]), "+f"(acc[1]), "+f"(acc[2]), "+f"(acc[3])
        : "r"(a0), "r"(a1), "r"(a2), "r"(a3), "r"(b0), "r"(b1));
}
__device__ __forceinline__ void cp16(uint32_t sdst, const void* gsrc) {
    asm volatile("cp.async.cg.shared.global [%0], [%1], 16;" :: "r"(sdst), "l"(gsrc));
}
__device__ __forceinline__ void cp_commit() {
    asm volatile("cp.async.commit_group;" ::: "memory");
}
template <int N>
__device__ __forceinline__ void cp_wait() {
    asm volatile("cp.async.wait_group %0;" :: "n"(N) : "memory");
}

// ---------------------------------------------------------------------------
// prep_kernel (unchanged, 20.7us):
//   blocks 0..159  : enc/dec projections (tf32 mma, M=32 N=128, K=64 chunks)
//   blocks 160..415: w2 -> g_w2p fp16 fragment pack
// ---------------------------------------------------------------------------
#define PA_STRIDE 272
#define PB_STRIDE 272
#define P_OFF_A   0
#define P_OFF_B   17408
#define P_SMEM    87040

__global__ __launch_bounds__(256) void prep_kernel(
    const float* __restrict__ enc, const float* __restrict__ dec,
    const float* __restrict__ w1, const float* __restrict__ b1,
    const float* __restrict__ w2)
{
    const int bid = blockIdx.x;
    const int tid = threadIdx.x;

    if (bid >= 160) {   // ---- w2 fp16 fragment pack ----
        int t  = (bid - 160) * 256 + tid;
        int l  = t & 31;
        int p  = (t >> 5) & 31;
        int ch = (t >> 10) & 15;
        int nt = t >> 14;
        int n  = nt * 256 + p * 8 + (l >> 2);
        int c0 = ch * 32 + (l & 3) * 2;
        const float* r = w2 + (size_t)n * H_;
        float2 v0 = *(const float2*)(r + c0);
        float2 v1 = *(const float2*)(r + c0 + 8);
        float2 v2 = *(const float2*)(r + c0 + 16);
        float2 v3 = *(const float2*)(r + c0 + 24);
        uint4 q;
        q.x = packh2(v0.x, v0.y);
        q.y = packh2(v1.x, v1.y);
        q.z = packh2(v2.x, v2.y);
        q.w = packh2(v3.x, v3.y);
        g_w2p[((size_t)(nt * 16 + ch) * 32 + p) * 32 + l] = q;
        return;
    }

    extern __shared__ char psm[];
    const uint32_t sbase = smem_u32(psm);

    const int ng = bid & 3;
    const int my = bid >> 2;
    const bool is_dec = (my >= 32);
    const float* A = is_dec ? dec : enc;
    const float* W = is_dec ? (w1 + D_) : w1;
    float* out     = is_dec ? g_dec : g_enc;
    const int m0   = (is_dec ? (my - 32) : my) * 32;
    const int n0   = ng * 128;

    const int lane = tid & 31;
    const int w    = tid >> 5;
    const int wm   = w >> 2;
    const int wn   = w & 3;
    float acc[4][4] = {};

    {
        if (tid < 128) {
            int j = tid;
            #pragma unroll
            for (int i = 0; i < 4; i++, j += 128) {
                int r = j >> 4, seg = j & 15;
                cp16(sbase + P_OFF_A + r * PA_STRIDE + seg * 16,
                     A + (size_t)(m0 + r) * D_ + seg * 4);
            }
        }
        int j = tid;
        #pragma unroll
        for (int i = 0; i < 8; i++, j += 256) {
            int r = j >> 4, seg = j & 15;
            cp16(sbase + P_OFF_B + r * PB_STRIDE + seg * 16,
                 W + (size_t)(n0 + r) * (2 * D_) + seg * 4);
        }
        cp_commit();
    }

    for (int cc = 0; cc < 8; cc++) {
        const int s = cc & 1;
        if (cc < 7) {
            const int sn = s ^ 1;
            const int k0 = (cc + 1) * 64;
            if (tid < 128) {
                int j = tid;
                #pragma unroll
                for (int i = 0; i < 4; i++, j += 128) {
                    int r = j >> 4, seg = j & 15;
                    cp16(sbase + P_OFF_A + sn * 8704 + r * PA_STRIDE + seg * 16,
                         A + (size_t)(m0 + r) * D_ + k0 + seg * 4);
                }
            }
            int j = tid;
            #pragma unroll
            for (int i = 0; i < 8; i++, j += 256) {
                int r = j >> 4, seg = j & 15;
                cp16(sbase + P_OFF_B + sn * 34816 + r * PB_STRIDE + seg * 16,
                     W + (size_t)(n0 + r) * (2 * D_) + k0 + seg * 4);
            }
            cp_commit();
            cp_wait<1>();
        } else {
            cp_wait<0>();
        }
        __syncthreads();

        const float* Af = (const float*)(psm + P_OFF_A + s * 8704);
        const float* Bf = (const float*)(psm + P_OFF_B + s * 34816);

        #pragma unroll
        for (int kk = 0; kk < 8; kk++) {
            int ar = wm * 16 + (lane >> 2);
            int ac = kk * 8 + (lane & 3);
            uint32_t a0 = f2tf32(Af[ar * 68 + ac]);
            uint32_t a1 = f2tf32(Af[(ar + 8) * 68 + ac]);
            uint32_t a2 = f2tf32(Af[ar * 68 + ac + 4]);
            uint32_t a3 = f2tf32(Af[(ar + 8) * 68 + ac + 4]);
            #pragma unroll
            for (int nf = 0; nf < 4; nf++) {
                int br = wn * 32 + nf * 8 + (lane >> 2);
                uint32_t b0 = f2tf32(Bf[br * 68 + ac]);
                uint32_t b1 = f2tf32(Bf[br * 68 + ac + 4]);
                mma_tf32(acc[nf], a0, a1, a2, a3, b0, b1);
            }
        }
        __syncthreads();
    }

    int row = m0 + wm * 16 + (lane >> 2);
    #pragma unroll
    for (int nf = 0; nf < 4; nf++) {
        int cg = n0 + wn * 32 + nf * 8 + (lane & 3) * 2;
        float bv0 = is_dec ? b1[cg]     : 0.0f;
        float bv1 = is_dec ? b1[cg + 1] : 0.0f;
        out[(size_t)row * H_ + cg]           = acc[nf][0] + bv0;
        out[(size_t)row * H_ + cg + 1]       = acc[nf][1] + bv1;
        out[(size_t)(row + 8) * H_ + cg]     = acc[nf][2] + bv0;
        out[(size_t)(row + 8) * H_ + cg + 1] = acc[nf][3] + bv1;
    }
}

// ---------------------------------------------------------------------------
// gemm_fused: one CTA per 128-row m-tile (grid 512).
//  Phase 1: A = gelu(enc+dec) fp16 frag-packed into 128KB SMEM (once).
//  Phase 2: 64 B chunks (16KB each) processed in PAIRS through a 6-stage
//           (3 stage-pair) cp.async pipeline; barrier once per pair.
// SMEM: A [0,131072), B pairs at 131072 + sp*32768, sp=0..2  => 229376 B.
// ---------------------------------------------------------------------------
#define FA_BYTES  131072
#define FB_STAGE  16384
#define SMEM_F    (FA_BYTES + 6 * FB_STAGE)   // 229376

__global__ __launch_bounds__(256) void gemm_fused(float* __restrict__ out)
{
    extern __shared__ char smem[];
    const uint32_t sbase = smem_u32(smem);
    const int tid  = threadIdx.x;
    const int lane = tid & 31;
    const int w    = tid >> 5;
    const int wm   = w >> 2;          // 0..1 (64 rows)
    const int wn   = w & 3;           // 0..3 (64 cols)
    const int mt   = blockIdx.x;      // 0..511

    const uint4* gB = g_w2p;

    // ---- prologue: prefetch pair 0 (chunks 0,1) and pair 1 (chunks 2,3) ----
    #pragma unroll
    for (int pp = 0; pp < 2; pp++) {
        uint32_t dB = sbase + FA_BYTES + pp * 2 * FB_STAGE + tid * 16;
        const uint4* pB = gB + pp * 2048 + tid;
        #pragma unroll
        for (int i = 0; i < 8; i++) cp16(dB + i * 4096, pB + i * 256);
        cp_commit();
    }

    // ---- Phase 1: A generation (fragment order, fp16) ----
    {
        const int l  = tid & 31;
        const int mb = (tid >> 5) & 7;
        const int rl = mb * 16 + (l >> 2);
        const int grow = mt * 128 + rl;
        const int bt   = grow >> 6;
        const int u    = grow & 63;
        const int bat  = grow >> 14;
        const float* ep  = g_enc + (size_t)bt * H_;
        const float* dp0 = g_dec + (size_t)(bat * 64 + u) * H_;
        const float* dp1 = dp0 + 8 * H_;
        uint4* sA = (uint4*)smem;

        #pragma unroll 2
        for (int ch = 0; ch < 16; ch++) {
            #pragma unroll
            for (int ks = 0; ks < 2; ks++) {
                int cb = ch * 32 + ks * 16 + (l & 3) * 2;
                float2 e0 = *(const float2*)(ep + cb);
                float2 e1 = *(const float2*)(ep + cb + 8);
                float2 a0 = *(const float2*)(dp0 + cb);
                float2 a1 = *(const float2*)(dp0 + cb + 8);
                float2 c0 = *(const float2*)(dp1 + cb);
                float2 c1 = *(const float2*)(dp1 + cb + 8);
                uint4 q;
                q.x = packh2(gelu_tanh(e0.x + a0.x), gelu_tanh(e0.y + a0.y));
                q.y = packh2(gelu_tanh(e0.x + c0.x), gelu_tanh(e0.y + c0.y));
                q.z = packh2(gelu_tanh(e1.x + a1.x), gelu_tanh(e1.y + a1.y));
                q.w = packh2(gelu_tanh(e1.x + c1.x), gelu_tanh(e1.y + c1.y));
                sA[(ch * 16 + mb * 2 + ks) * 32 + l] = q;
            }
        }
    }

    // ---- Phase 2: 32 chunk-pairs, one barrier per pair ----
    const size_t rbase = (size_t)mt * 128;
    float acc[4][8][4] = {};

    for (int jp = 0; jp < 32; jp++) {
        cp_wait<1>();        // pair jp complete (pair jp+1 still in flight)
        __syncthreads();     // all warps done with pair jp-1; its stages are free

        // prefetch pair jp+2 into stage-pair (jp+2)%3 == (jp-1)%3 adjacency-safe
        if (jp + 2 < 32) {
            const int sp2 = (jp + 2) % 3;
            uint32_t dB = sbase + FA_BYTES + sp2 * 2 * FB_STAGE + tid * 16;
            const uint4* pB = gB + (size_t)(2 * jp + 4) * 1024 + tid;
            #pragma unroll
            for (int i = 0; i < 8; i++) cp16(dB + i * 4096, pB + i * 256);
        }
        cp_commit();

        const int sp = jp % 3;
        #pragma unroll
        for (int cc = 0; cc < 2; cc++) {
            const int ch = (2 * jp + cc) & 15;
            const uint4* sA = (const uint4*)smem + ch * 512;
            const uint4* sB = (const uint4*)(smem + FA_BYTES + (sp * 2 + cc) * FB_STAGE);

            uint4 bf[8];
            #pragma unroll
            for (int p = 0; p < 8; p++)
                bf[p] = sB[(wn * 8 + p) * 32 + lane];

            #pragma unroll
            for (int ks = 0; ks < 2; ks++) {
                uint4 af[4];
                #pragma unroll
                for (int mb = 0; mb < 4; mb++)
                    af[mb] = sA[((wm * 4 + mb) * 2 + ks) * 32 + lane];
                #pragma unroll
                for (int mb = 0; mb < 4; mb++) {
                    #pragma unroll
                    for (int p = 0; p < 8; p++) {
                        uint32_t b0 = ks ? bf[p].z : bf[p].x;
                        uint32_t b1 = ks ? bf[p].w : bf[p].y;
                        mma_f16(acc[mb][p], af[mb].x, af[mb].y, af[mb].z, af[mb].w,
                                b0, b1);
                    }
                }
            }
        }

        // epilogue after each 8-pair group (one nt of 256 columns)
        if ((jp & 7) == 7) {
            const int nt = jp >> 3;
            #pragma unroll
            for (int mb = 0; mb < 4; mb++) {
                size_t r = rbase + wm * 64 + mb * 16 + (lane >> 2);
                #pragma unroll
                for (int p = 0; p < 8; p++) {
                    int cg = nt * 256 + wn * 64 + p * 8 + (lane & 3) * 2;
                    *(float2*)(out + r * V_ + cg) =
                        make_float2(acc[mb][p][0], acc[mb][p][1]);
                    *(float2*)(out + (r + 8) * V_ + cg) =
                        make_float2(acc[mb][p][2], acc[mb][p][3]);
                    acc[mb][p][0] = 0.0f; acc[mb][p][1] = 0.0f;
                    acc[mb][p][2] = 0.0f; acc[mb][p][3] = 0.0f;
                }
            }
        }
    }
}

extern "C" void kernel_launch(void* const* d_in, const int* in_sizes, int n_in,
                              void* d_out, int out_size) {
    const float* enc = (const float*)d_in[0];
    const float* dec = (const float*)d_in[1];
    const float* w1  = (const float*)d_in[2];
    const float* b1  = (const float*)d_in[3];
    const float* w2  = (const float*)d_in[4];
    float* out = (float*)d_out;

    cudaFuncSetAttribute(prep_kernel, cudaFuncAttributeMaxDynamicSharedMemorySize, P_SMEM);
    cudaFuncSetAttribute(gemm_fused, cudaFuncAttributeMaxDynamicSharedMemorySize, SMEM_F);
    prep_kernel<<<416, 256, P_SMEM>>>(enc, dec, w1, b1, w2);
    gemm_fused<<<512, 256, SMEM_F>>>(out);
}